// round 1
// baseline (speedup 1.0000x reference)
#include <cuda_runtime.h>
#include <math.h>

#define BATCH 2
#define CIN 256
#define CQKV 768
#define NHEADS 8
#define HDIM 32
#define NPIX 4096
#define EPSV 1e-4f

// ---------------- device scratch (no allocations allowed) ----------------
__device__ float g_wqkv[CQKV * CIN];                    // normalized qkv weights
__device__ float g_wout[CIN * CIN];                     // normalized out weights
__device__ float g_qkv[BATCH * CQKV * NPIX];            // qkv conv output
__device__ float g_q[BATCH * NHEADS * NPIX * HDIM];     // normalized q [b,h,N,d]
__device__ float g_k[BATCH * NHEADS * NPIX * HDIM];
__device__ float g_v[BATCH * NHEADS * NPIX * HDIM];
__device__ float g_yt[BATCH * NPIX * CIN];              // attention out, [b,pix,ch]

// ---------------- kernel 1: weight norm ----------------
// result = w * inv_sqrt_fan / (EPS + inv_sqrt_fan * ||w||),  fan=256, inv=1/16
__global__ void wnorm_kernel(const float* __restrict__ w, int which) {
    float* o = which ? g_wout : g_wqkv;
    const int r = blockIdx.x;
    const int t = threadIdx.x;
    float v = w[r * CIN + t];
    __shared__ float red[256];
    red[t] = v * v;
    __syncthreads();
    #pragma unroll
    for (int s = 128; s > 0; s >>= 1) {
        if (t < s) red[t] += red[t + s];
        __syncthreads();
    }
    float n = sqrtf(red[0]);
    float scale = 0.0625f / (EPSV + 0.0625f * n);
    o[r * CIN + t] = v * scale;
}

// ---------------- kernel 2: QKV GEMM  C[b,768,4096] = Wqkv[768,256] * X[b,256,4096]
__global__ void __launch_bounds__(256) qkv_gemm_kernel(const float* __restrict__ x) {
    const int bn = blockIdx.x * 64;
    const int bm = blockIdx.y * 64;
    const int b  = blockIdx.z;
    const float* Bg = x + (size_t)b * CIN * NPIX;
    float* Cg = g_qkv + (size_t)b * CQKV * NPIX;

    __shared__ float As[16][65];   // [kk][m]
    __shared__ float Bs[16][68];   // [kk][n]

    const int tid = threadIdx.x;
    const int tx = tid & 15, ty = tid >> 4;

    float acc[4][4];
    #pragma unroll
    for (int i = 0; i < 4; ++i)
        #pragma unroll
        for (int j = 0; j < 4; ++j) acc[i][j] = 0.f;

    for (int k0 = 0; k0 < CIN; k0 += 16) {
        __syncthreads();
        #pragma unroll
        for (int i = 0; i < 4; ++i) {
            int idx = tid + i * 256;
            int m = idx >> 4, kk = idx & 15;
            As[kk][m] = g_wqkv[(bm + m) * CIN + k0 + kk];
        }
        #pragma unroll
        for (int i = 0; i < 4; ++i) {
            int idx = tid + i * 256;
            int kk = idx >> 6, n = idx & 63;
            Bs[kk][n] = Bg[(size_t)(k0 + kk) * NPIX + bn + n];
        }
        __syncthreads();
        #pragma unroll
        for (int kk = 0; kk < 16; ++kk) {
            float a0 = As[kk][ty * 4 + 0];
            float a1 = As[kk][ty * 4 + 1];
            float a2 = As[kk][ty * 4 + 2];
            float a3 = As[kk][ty * 4 + 3];
            float4 bv = *(float4*)&Bs[kk][tx * 4];
            acc[0][0] += a0 * bv.x; acc[0][1] += a0 * bv.y; acc[0][2] += a0 * bv.z; acc[0][3] += a0 * bv.w;
            acc[1][0] += a1 * bv.x; acc[1][1] += a1 * bv.y; acc[1][2] += a1 * bv.z; acc[1][3] += a1 * bv.w;
            acc[2][0] += a2 * bv.x; acc[2][1] += a2 * bv.y; acc[2][2] += a2 * bv.z; acc[2][3] += a2 * bv.w;
            acc[3][0] += a3 * bv.x; acc[3][1] += a3 * bv.y; acc[3][2] += a3 * bv.z; acc[3][3] += a3 * bv.w;
        }
    }
    #pragma unroll
    for (int i = 0; i < 4; ++i) {
        float4 st = make_float4(acc[i][0], acc[i][1], acc[i][2], acc[i][3]);
        *(float4*)&Cg[(size_t)(bm + ty * 4 + i) * NPIX + bn + tx * 4] = st;
    }
}

// ---------------- kernel 3: pixel-norm + split into [b,h,N,d] ----------------
__global__ void norm_split_kernel() {
    int t = blockIdx.x * blockDim.x + threadIdx.x;     // 65536 threads
    int pix = t & (NPIX - 1);
    int bh = t >> 12;                                   // 0..15
    int b = bh >> 3, h = bh & 7;
    const float* base = g_qkv + (size_t)b * CQKV * NPIX;

    #pragma unroll
    for (int s = 0; s < 3; ++s) {
        float* outp = (s == 0) ? g_q : (s == 1) ? g_k : g_v;
        const float* p = base + (size_t)(s * 256 + h * 32) * NPIX + pix;
        float r[32];
        float ss = 0.f;
        #pragma unroll
        for (int d = 0; d < 32; ++d) {
            r[d] = p[(size_t)d * NPIX];
            ss += r[d] * r[d];
        }
        float sc = rsqrtf(ss * (1.0f / 32.0f) + EPSV);
        float* o = outp + ((size_t)bh * NPIX + pix) * HDIM;
        #pragma unroll
        for (int d4 = 0; d4 < 8; ++d4) {
            float4 v4 = make_float4(r[d4 * 4 + 0] * sc, r[d4 * 4 + 1] * sc,
                                    r[d4 * 4 + 2] * sc, r[d4 * 4 + 3] * sc);
            *(float4*)(o + d4 * 4) = v4;
        }
    }
}

// ---------------- kernel 4: flash attention ----------------
// grid (64 qtiles, 16 bh), 256 threads. BM=BN=64, d=32.
__global__ void __launch_bounds__(256) attn_kernel() {
    const int qb = blockIdx.x;
    const int bh = blockIdx.y;
    const int tid = threadIdx.x;

    const float* Qg = g_q + ((size_t)bh * NPIX + qb * 64) * HDIM;
    const float* Kg = g_k + (size_t)bh * NPIX * HDIM;
    const float* Vg = g_v + (size_t)bh * NPIX * HDIM;

    __shared__ float sQ[64][36];
    __shared__ float sK[64][36];
    __shared__ float sV[64][36];
    __shared__ float sS[64][65];
    __shared__ float sM[64], sL[64];

    // load Q tile
    #pragma unroll
    for (int i = 0; i < 2; ++i) {
        int f4 = tid + i * 256;
        int row = f4 >> 3, dd = (f4 & 7) * 4;
        *(float4*)&sQ[row][dd] = *(const float4*)(Qg + row * HDIM + dd);
    }
    if (tid < 64) { sM[tid] = -1e30f; sL[tid] = 0.f; }

    float oacc[8];
    #pragma unroll
    for (int j = 0; j < 8; ++j) oacc[j] = 0.f;

    const int ty = tid >> 4, tx = tid & 15;
    const int r = tid >> 2, pgrp = tid & 3;
    const int cg = pgrp * 8;
    const float scale = 0.17677669529663687f;   // 1/sqrt(32)

    for (int kt = 0; kt < 64; ++kt) {
        __syncthreads();
        #pragma unroll
        for (int i = 0; i < 2; ++i) {
            int f4 = tid + i * 256;
            int row = f4 >> 3, dd = (f4 & 7) * 4;
            *(float4*)&sK[row][dd] = *(const float4*)(Kg + (size_t)(kt * 64 + row) * HDIM + dd);
            *(float4*)&sV[row][dd] = *(const float4*)(Vg + (size_t)(kt * 64 + row) * HDIM + dd);
        }
        __syncthreads();

        // S = Q K^T, 4x4 per thread
        float acc[4][4];
        #pragma unroll
        for (int i = 0; i < 4; ++i)
            #pragma unroll
            for (int j = 0; j < 4; ++j) acc[i][j] = 0.f;

        #pragma unroll
        for (int d4 = 0; d4 < 8; ++d4) {
            float4 qv[4], kv[4];
            #pragma unroll
            for (int i = 0; i < 4; ++i) qv[i] = *(float4*)&sQ[ty * 4 + i][d4 * 4];
            #pragma unroll
            for (int j = 0; j < 4; ++j) kv[j] = *(float4*)&sK[tx * 4 + j][d4 * 4];
            #pragma unroll
            for (int i = 0; i < 4; ++i)
                #pragma unroll
                for (int j = 0; j < 4; ++j) {
                    acc[i][j] += qv[i].x * kv[j].x;
                    acc[i][j] += qv[i].y * kv[j].y;
                    acc[i][j] += qv[i].z * kv[j].z;
                    acc[i][j] += qv[i].w * kv[j].w;
                }
        }
        #pragma unroll
        for (int i = 0; i < 4; ++i)
            #pragma unroll
            for (int j = 0; j < 4; ++j)
                sS[ty * 4 + i][tx * 4 + j] = acc[i][j] * scale;
        __syncthreads();

        // online softmax: 4 threads per row, 16 cols each
        float mt = -1e30f;
        #pragma unroll
        for (int j = 0; j < 16; ++j) mt = fmaxf(mt, sS[r][pgrp * 16 + j]);
        mt = fmaxf(mt, __shfl_xor_sync(0xffffffffu, mt, 1));
        mt = fmaxf(mt, __shfl_xor_sync(0xffffffffu, mt, 2));
        float mold = sM[r];
        float mnew = fmaxf(mold, mt);
        float fsc = __expf(mold - mnew);
        float lsum = 0.f;
        #pragma unroll
        for (int j = 0; j < 16; ++j) {
            float e = __expf(sS[r][pgrp * 16 + j] - mnew);
            sS[r][pgrp * 16 + j] = e;
            lsum += e;
        }
        lsum += __shfl_xor_sync(0xffffffffu, lsum, 1);
        lsum += __shfl_xor_sync(0xffffffffu, lsum, 2);
        if (pgrp == 0) { sM[r] = mnew; sL[r] = sL[r] * fsc + lsum; }
        __syncthreads();

        // O update: row r, 8 cols starting at cg
        #pragma unroll
        for (int j = 0; j < 8; ++j) oacc[j] *= fsc;
        #pragma unroll 8
        for (int kk = 0; kk < 64; ++kk) {
            float pk = sS[r][kk];
            float4 va = *(float4*)&sV[kk][cg];
            float4 vb = *(float4*)&sV[kk][cg + 4];
            oacc[0] += pk * va.x; oacc[1] += pk * va.y;
            oacc[2] += pk * va.z; oacc[3] += pk * va.w;
            oacc[4] += pk * vb.x; oacc[5] += pk * vb.y;
            oacc[6] += pk * vb.z; oacc[7] += pk * vb.w;
        }
    }

    float invl = 1.0f / sL[r];
    int b = bh >> 3, h = bh & 7;
    float* o = g_yt + ((size_t)b * NPIX + qb * 64 + r) * CIN + h * 32 + cg;
    float4 w1 = make_float4(oacc[0] * invl, oacc[1] * invl, oacc[2] * invl, oacc[3] * invl);
    float4 w2 = make_float4(oacc[4] * invl, oacc[5] * invl, oacc[6] * invl, oacc[7] * invl);
    *(float4*)(o + 0) = w1;
    *(float4*)(o + 4) = w2;
}

// ---------------- kernel 5: out GEMM + mp_add ----------------
// C[b,256,4096] = Wout[256,256] * Y[b,256,4096], Y stored transposed as g_yt[b,pix,ch]
__global__ void __launch_bounds__(256) out_gemm_kernel(const float* __restrict__ x,
                                                       float* __restrict__ out) {
    const int bn = blockIdx.x * 64;
    const int bm = blockIdx.y * 64;
    const int b  = blockIdx.z;
    const float* Yg = g_yt + (size_t)b * NPIX * CIN;

    __shared__ float As[16][65];
    __shared__ float Bs[16][68];

    const int tid = threadIdx.x;
    const int tx = tid & 15, ty = tid >> 4;

    float acc[4][4];
    #pragma unroll
    for (int i = 0; i < 4; ++i)
        #pragma unroll
        for (int j = 0; j < 4; ++j) acc[i][j] = 0.f;

    for (int k0 = 0; k0 < CIN; k0 += 16) {
        __syncthreads();
        #pragma unroll
        for (int i = 0; i < 4; ++i) {
            int idx = tid + i * 256;
            int m = idx >> 4, kk = idx & 15;
            As[kk][m] = g_wout[(bm + m) * CIN + k0 + kk];
        }
        #pragma unroll
        for (int i = 0; i < 4; ++i) {
            int idx = tid + i * 256;
            int n = idx >> 4, kk = idx & 15;
            Bs[kk][n] = Yg[(size_t)(bn + n) * CIN + k0 + kk];
        }
        __syncthreads();
        #pragma unroll
        for (int kk = 0; kk < 16; ++kk) {
            float a0 = As[kk][ty * 4 + 0];
            float a1 = As[kk][ty * 4 + 1];
            float a2 = As[kk][ty * 4 + 2];
            float a3 = As[kk][ty * 4 + 3];
            float4 bv = *(float4*)&Bs[kk][tx * 4];
            acc[0][0] += a0 * bv.x; acc[0][1] += a0 * bv.y; acc[0][2] += a0 * bv.z; acc[0][3] += a0 * bv.w;
            acc[1][0] += a1 * bv.x; acc[1][1] += a1 * bv.y; acc[1][2] += a1 * bv.z; acc[1][3] += a1 * bv.w;
            acc[2][0] += a2 * bv.x; acc[2][1] += a2 * bv.y; acc[2][2] += a2 * bv.z; acc[2][3] += a2 * bv.w;
            acc[3][0] += a3 * bv.x; acc[3][1] += a3 * bv.y; acc[3][2] += a3 * bv.z; acc[3][3] += a3 * bv.w;
        }
    }

    // mp_add: ((1-t)x + t*y) / sqrt(t^2 + (1-t)^2),  t = 0.3
    const float a1c = 0.9191450300180579f;   // 0.7 / sqrt(0.58)
    const float a2c = 0.3939192985791676f;   // 0.3 / sqrt(0.58)
    #pragma unroll
    for (int i = 0; i < 4; ++i) {
        int row = bm + ty * 4 + i;
        size_t off = ((size_t)b * CIN + row) * NPIX + bn + tx * 4;
        float4 xv = *(const float4*)&x[off];
        float4 st;
        st.x = a1c * xv.x + a2c * acc[i][0];
        st.y = a1c * xv.y + a2c * acc[i][1];
        st.z = a1c * xv.z + a2c * acc[i][2];
        st.w = a1c * xv.w + a2c * acc[i][3];
        *(float4*)&out[off] = st;
    }
}

// ---------------- launch ----------------
extern "C" void kernel_launch(void* const* d_in, const int* in_sizes, int n_in,
                              void* d_out, int out_size) {
    const float* x    = (const float*)d_in[0];
    const float* wqkv = (const float*)d_in[1];
    const float* wout = (const float*)d_in[2];
    float* out = (float*)d_out;

    wnorm_kernel<<<CQKV, 256>>>(wqkv, 0);
    wnorm_kernel<<<CIN, 256>>>(wout, 1);
    qkv_gemm_kernel<<<dim3(NPIX / 64, CQKV / 64, BATCH), 256>>>(x);
    norm_split_kernel<<<(BATCH * NHEADS * NPIX) / 256, 256>>>();
    attn_kernel<<<dim3(NPIX / 64, BATCH * NHEADS), 256>>>();
    out_gemm_kernel<<<dim3(NPIX / 64, CIN / 64, BATCH), 256>>>(x, out);
}

// round 2
// speedup vs baseline: 7.3639x; 7.3639x over previous
#include <cuda_runtime.h>
#include <cuda_fp16.h>
#include <math.h>

#define BATCH 2
#define CIN 256
#define CQKV 768
#define NHEADS 8
#define HDIM 32
#define NPIX 4096
#define EPSV 1e-4f
#define NBH (BATCH * NHEADS)

// padded smem strides (halves) — chosen conflict-free for the fragment access patterns
#define PADK 40
#define PADV 72

// ---------------- device scratch (no allocations allowed) ----------------
__device__ float  g_wqkv[CQKV * CIN];
__device__ float  g_wout[CIN * CIN];
__device__ float  g_qkv[BATCH * CQKV * NPIX];
__device__ __half g_qh[NBH * NPIX * HDIM];    // normalized q * softmax-scale*log2e, [bh][pix][d]
__device__ __half g_kh[NBH * NPIX * HDIM];    // normalized k, [bh][pix][d]
__device__ __half g_vt[NBH * HDIM * NPIX];    // normalized v TRANSPOSED, [bh][d][pix]
__device__ float  g_yt[BATCH * NPIX * CIN];   // attention out, [b][pix][ch]

// ---------------- kernel 1: weight norm ----------------
__global__ void wnorm_kernel(const float* __restrict__ w, int which) {
    float* o = which ? g_wout : g_wqkv;
    const int r = blockIdx.x;
    const int t = threadIdx.x;
    float v = w[r * CIN + t];
    __shared__ float red[256];
    red[t] = v * v;
    __syncthreads();
    #pragma unroll
    for (int s = 128; s > 0; s >>= 1) {
        if (t < s) red[t] += red[t + s];
        __syncthreads();
    }
    float n = sqrtf(red[0]);
    float scale = 0.0625f / (EPSV + 0.0625f * n);
    o[r * CIN + t] = v * scale;
}

// ---------------- kernel 2: QKV GEMM (fp32) ----------------
__global__ void __launch_bounds__(256) qkv_gemm_kernel(const float* __restrict__ x) {
    const int bn = blockIdx.x * 64;
    const int bm = blockIdx.y * 64;
    const int b  = blockIdx.z;
    const float* Bg = x + (size_t)b * CIN * NPIX;
    float* Cg = g_qkv + (size_t)b * CQKV * NPIX;

    __shared__ float As[16][65];
    __shared__ float Bs[16][68];

    const int tid = threadIdx.x;
    const int tx = tid & 15, ty = tid >> 4;

    float acc[4][4];
    #pragma unroll
    for (int i = 0; i < 4; ++i)
        #pragma unroll
        for (int j = 0; j < 4; ++j) acc[i][j] = 0.f;

    for (int k0 = 0; k0 < CIN; k0 += 16) {
        __syncthreads();
        #pragma unroll
        for (int i = 0; i < 4; ++i) {
            int idx = tid + i * 256;
            int m = idx >> 4, kk = idx & 15;
            As[kk][m] = g_wqkv[(bm + m) * CIN + k0 + kk];
        }
        #pragma unroll
        for (int i = 0; i < 4; ++i) {
            int idx = tid + i * 256;
            int kk = idx >> 6, n = idx & 63;
            Bs[kk][n] = Bg[(size_t)(k0 + kk) * NPIX + bn + n];
        }
        __syncthreads();
        #pragma unroll
        for (int kk = 0; kk < 16; ++kk) {
            float a0 = As[kk][ty * 4 + 0];
            float a1 = As[kk][ty * 4 + 1];
            float a2 = As[kk][ty * 4 + 2];
            float a3 = As[kk][ty * 4 + 3];
            float4 bv = *(float4*)&Bs[kk][tx * 4];
            acc[0][0] += a0 * bv.x; acc[0][1] += a0 * bv.y; acc[0][2] += a0 * bv.z; acc[0][3] += a0 * bv.w;
            acc[1][0] += a1 * bv.x; acc[1][1] += a1 * bv.y; acc[1][2] += a1 * bv.z; acc[1][3] += a1 * bv.w;
            acc[2][0] += a2 * bv.x; acc[2][1] += a2 * bv.y; acc[2][2] += a2 * bv.z; acc[2][3] += a2 * bv.w;
            acc[3][0] += a3 * bv.x; acc[3][1] += a3 * bv.y; acc[3][2] += a3 * bv.z; acc[3][3] += a3 * bv.w;
        }
    }
    #pragma unroll
    for (int i = 0; i < 4; ++i) {
        float4 st = make_float4(acc[i][0], acc[i][1], acc[i][2], acc[i][3]);
        *(float4*)&Cg[(size_t)(bm + ty * 4 + i) * NPIX + bn + tx * 4] = st;
    }
}

// ---------------- kernel 3: pixel-norm + split + fp16 convert ----------------
// q gets softmax scale (1/sqrt(32)) * log2(e) folded in (exp2 domain softmax).
__global__ void norm_split_kernel() {
    const float QSC = 0.17677669529663687f * 1.4426950408889634f;
    int t = blockIdx.x * blockDim.x + threadIdx.x;     // 65536 threads
    int pix = t & (NPIX - 1);
    int bh = t >> 12;
    int b = bh >> 3, h = bh & 7;
    const float* base = g_qkv + (size_t)b * CQKV * NPIX;

    #pragma unroll
    for (int s = 0; s < 3; ++s) {
        const float* p = base + (size_t)(s * 256 + h * 32) * NPIX + pix;
        float r[32];
        float ss = 0.f;
        #pragma unroll
        for (int d = 0; d < 32; ++d) {
            r[d] = p[(size_t)d * NPIX];
            ss += r[d] * r[d];
        }
        float sc = rsqrtf(ss * (1.0f / 32.0f) + EPSV);
        if (s == 0) {
            __half* o = g_qh + ((size_t)bh * NPIX + pix) * HDIM;
            float qs = sc * QSC;
            #pragma unroll
            for (int d2 = 0; d2 < 16; ++d2)
                *(__half2*)(o + d2 * 2) = __floats2half2_rn(r[d2 * 2] * qs, r[d2 * 2 + 1] * qs);
        } else if (s == 1) {
            __half* o = g_kh + ((size_t)bh * NPIX + pix) * HDIM;
            #pragma unroll
            for (int d2 = 0; d2 < 16; ++d2)
                *(__half2*)(o + d2 * 2) = __floats2half2_rn(r[d2 * 2] * sc, r[d2 * 2 + 1] * sc);
        } else {
            // transposed store: [bh][d][pix]
            #pragma unroll
            for (int d = 0; d < 32; ++d)
                g_vt[((size_t)bh * HDIM + d) * NPIX + pix] = __float2half_rn(r[d] * sc);
        }
    }
}

// ---------------- mma helper ----------------
__device__ __forceinline__ void mma16816(float c[4],
                                         unsigned a0, unsigned a1, unsigned a2, unsigned a3,
                                         unsigned b0, unsigned b1) {
    asm volatile(
        "mma.sync.aligned.m16n8k16.row.col.f32.f16.f16.f32 "
        "{%0,%1,%2,%3}, {%4,%5,%6,%7}, {%8,%9}, {%0,%1,%2,%3};"
        : "+f"(c[0]), "+f"(c[1]), "+f"(c[2]), "+f"(c[3])
        : "r"(a0), "r"(a1), "r"(a2), "r"(a3), "r"(b0), "r"(b1));
}

// ---------------- kernel 4: flash attention (HMMA fp16, fp32 accum) ----------------
// grid (64 qtiles, 16 bh), 128 threads = 4 warps. Each warp owns 16 Q rows.
__global__ void __launch_bounds__(128) attn_mma_kernel() {
    const int qb = blockIdx.x;
    const int bh = blockIdx.y;
    const int tid = threadIdx.x;
    const int w = tid >> 5, lane = tid & 31;
    const int lq = lane >> 2;        // 0..7
    const int lr = lane & 3;         // 0..3

    const __half* Qg = g_qh + ((size_t)bh * NPIX + qb * 64) * HDIM;
    const __half* Kg = g_kh + (size_t)bh * NPIX * HDIM;
    const __half* Vg = g_vt + (size_t)bh * HDIM * NPIX;

    __shared__ __half sQ[64 * PADK];
    __shared__ __half sK[64 * PADK];
    __shared__ __half sVt[32 * PADV];

    // load Q tile (64x32 halves)
    #pragma unroll
    for (int i = tid; i < 256; i += 128) {
        int row = i >> 2, seg = i & 3;
        *(uint4*)&sQ[row * PADK + seg * 8] = *(const uint4*)(Qg + row * 32 + seg * 8);
    }
    __syncthreads();

    // Q fragments (reused across all 64 k-tiles): rows r0 = w*16+lq, r1 = r0+8
    const int r0 = w * 16 + lq;
    const int r1 = r0 + 8;
    unsigned qf[2][4];
    #pragma unroll
    for (int ks = 0; ks < 2; ++ks) {
        qf[ks][0] = *(unsigned*)&sQ[r0 * PADK + ks * 16 + lr * 2];
        qf[ks][1] = *(unsigned*)&sQ[r1 * PADK + ks * 16 + lr * 2];
        qf[ks][2] = *(unsigned*)&sQ[r0 * PADK + ks * 16 + lr * 2 + 8];
        qf[ks][3] = *(unsigned*)&sQ[r1 * PADK + ks * 16 + lr * 2 + 8];
    }

    float m0 = -1e30f, m1 = -1e30f, l0 = 0.f, l1 = 0.f;
    float o[4][4];
    #pragma unroll
    for (int i = 0; i < 4; ++i)
        #pragma unroll
        for (int j = 0; j < 4; ++j) o[i][j] = 0.f;

    for (int kt = 0; kt < 64; ++kt) {
        __syncthreads();
        // K tile [64][32] -> sK
        const __half* Kt = Kg + (size_t)kt * 64 * 32;
        #pragma unroll
        for (int i = tid; i < 256; i += 128) {
            int row = i >> 2, seg = i & 3;
            *(uint4*)&sK[row * PADK + seg * 8] = *(const uint4*)(Kt + row * 32 + seg * 8);
        }
        // Vt tile [32][64] -> sVt (rows are d, contiguous along keys)
        #pragma unroll
        for (int i = tid; i < 256; i += 128) {
            int row = i >> 3, seg = i & 7;
            *(uint4*)&sVt[row * PADV + seg * 8] =
                *(const uint4*)(Vg + (size_t)row * NPIX + kt * 64 + seg * 8);
        }
        __syncthreads();

        // ---- S = Q K^T : 8 n-tiles x 2 k-steps ----
        float s[8][4];
        #pragma unroll
        for (int j = 0; j < 8; ++j) {
            s[j][0] = s[j][1] = s[j][2] = s[j][3] = 0.f;
            #pragma unroll
            for (int ks = 0; ks < 2; ++ks) {
                int krow = j * 8 + lq;
                unsigned b0 = *(unsigned*)&sK[krow * PADK + ks * 16 + lr * 2];
                unsigned b1 = *(unsigned*)&sK[krow * PADK + ks * 16 + lr * 2 + 8];
                mma16816(s[j], qf[ks][0], qf[ks][1], qf[ks][2], qf[ks][3], b0, b1);
            }
        }

        // ---- online softmax (exp2 domain; scale folded into Q) ----
        float mt0 = -1e30f, mt1 = -1e30f;
        #pragma unroll
        for (int j = 0; j < 8; ++j) {
            mt0 = fmaxf(mt0, fmaxf(s[j][0], s[j][1]));
            mt1 = fmaxf(mt1, fmaxf(s[j][2], s[j][3]));
        }
        mt0 = fmaxf(mt0, __shfl_xor_sync(0xffffffffu, mt0, 1));
        mt0 = fmaxf(mt0, __shfl_xor_sync(0xffffffffu, mt0, 2));
        mt1 = fmaxf(mt1, __shfl_xor_sync(0xffffffffu, mt1, 1));
        mt1 = fmaxf(mt1, __shfl_xor_sync(0xffffffffu, mt1, 2));
        float mn0 = fmaxf(m0, mt0), mn1 = fmaxf(m1, mt1);
        float f0 = exp2f(m0 - mn0), f1 = exp2f(m1 - mn1);
        m0 = mn0; m1 = mn1;

        unsigned pa[4][4];     // A fragments for PV: [k-step over keys][reg]
        float ls0 = 0.f, ls1 = 0.f;
        #pragma unroll
        for (int j = 0; j < 8; ++j) {
            float p0 = exp2f(s[j][0] - m0);
            float p1 = exp2f(s[j][1] - m0);
            float p2 = exp2f(s[j][2] - m1);
            float p3 = exp2f(s[j][3] - m1);
            ls0 += p0 + p1; ls1 += p2 + p3;
            __half2 h01 = __floats2half2_rn(p0, p1);
            __half2 h23 = __floats2half2_rn(p2, p3);
            int kk2 = j >> 1, hi = (j & 1) * 2;
            pa[kk2][hi + 0] = *(unsigned*)&h01;
            pa[kk2][hi + 1] = *(unsigned*)&h23;
        }
        l0 = l0 * f0 + ls0;
        l1 = l1 * f1 + ls1;

        #pragma unroll
        for (int nt = 0; nt < 4; ++nt) {
            o[nt][0] *= f0; o[nt][1] *= f0;
            o[nt][2] *= f1; o[nt][3] *= f1;
        }

        // ---- O += P V : 4 k-steps (keys) x 4 n-tiles (d) ----
        #pragma unroll
        for (int kk2 = 0; kk2 < 4; ++kk2) {
            #pragma unroll
            for (int nt = 0; nt < 4; ++nt) {
                int drow = nt * 8 + lq;
                unsigned b0 = *(unsigned*)&sVt[drow * PADV + kk2 * 16 + lr * 2];
                unsigned b1 = *(unsigned*)&sVt[drow * PADV + kk2 * 16 + lr * 2 + 8];
                mma16816(o[nt], pa[kk2][0], pa[kk2][1], pa[kk2][2], pa[kk2][3], b0, b1);
            }
        }
    }

    // final row-sum reduce + write
    l0 += __shfl_xor_sync(0xffffffffu, l0, 1);
    l0 += __shfl_xor_sync(0xffffffffu, l0, 2);
    l1 += __shfl_xor_sync(0xffffffffu, l1, 1);
    l1 += __shfl_xor_sync(0xffffffffu, l1, 2);
    float inv0 = 1.0f / l0, inv1 = 1.0f / l1;

    int b = bh >> 3, h = bh & 7;
    float* O0 = g_yt + ((size_t)b * NPIX + qb * 64 + r0) * CIN + h * 32;
    float* O1 = g_yt + ((size_t)b * NPIX + qb * 64 + r1) * CIN + h * 32;
    #pragma unroll
    for (int nt = 0; nt < 4; ++nt) {
        int col = nt * 8 + lr * 2;
        float2 v0 = make_float2(o[nt][0] * inv0, o[nt][1] * inv0);
        float2 v1 = make_float2(o[nt][2] * inv1, o[nt][3] * inv1);
        *(float2*)(O0 + col) = v0;
        *(float2*)(O1 + col) = v1;
    }
}

// ---------------- kernel 5: out GEMM + mp_add (fp32) ----------------
__global__ void __launch_bounds__(256) out_gemm_kernel(const float* __restrict__ x,
                                                       float* __restrict__ out) {
    const int bn = blockIdx.x * 64;
    const int bm = blockIdx.y * 64;
    const int b  = blockIdx.z;
    const float* Yg = g_yt + (size_t)b * NPIX * CIN;

    __shared__ float As[16][65];
    __shared__ float Bs[16][68];

    const int tid = threadIdx.x;
    const int tx = tid & 15, ty = tid >> 4;

    float acc[4][4];
    #pragma unroll
    for (int i = 0; i < 4; ++i)
        #pragma unroll
        for (int j = 0; j < 4; ++j) acc[i][j] = 0.f;

    for (int k0 = 0; k0 < CIN; k0 += 16) {
        __syncthreads();
        #pragma unroll
        for (int i = 0; i < 4; ++i) {
            int idx = tid + i * 256;
            int m = idx >> 4, kk = idx & 15;
            As[kk][m] = g_wout[(bm + m) * CIN + k0 + kk];
        }
        #pragma unroll
        for (int i = 0; i < 4; ++i) {
            int idx = tid + i * 256;
            int n = idx >> 4, kk = idx & 15;
            Bs[kk][n] = Yg[(size_t)(bn + n) * CIN + k0 + kk];
        }
        __syncthreads();
        #pragma unroll
        for (int kk = 0; kk < 16; ++kk) {
            float a0 = As[kk][ty * 4 + 0];
            float a1 = As[kk][ty * 4 + 1];
            float a2 = As[kk][ty * 4 + 2];
            float a3 = As[kk][ty * 4 + 3];
            float4 bv = *(float4*)&Bs[kk][tx * 4];
            acc[0][0] += a0 * bv.x; acc[0][1] += a0 * bv.y; acc[0][2] += a0 * bv.z; acc[0][3] += a0 * bv.w;
            acc[1][0] += a1 * bv.x; acc[1][1] += a1 * bv.y; acc[1][2] += a1 * bv.z; acc[1][3] += a1 * bv.w;
            acc[2][0] += a2 * bv.x; acc[2][1] += a2 * bv.y; acc[2][2] += a2 * bv.z; acc[2][3] += a2 * bv.w;
            acc[3][0] += a3 * bv.x; acc[3][1] += a3 * bv.y; acc[3][2] += a3 * bv.z; acc[3][3] += a3 * bv.w;
        }
    }

    const float a1c = 0.9191450300180579f;   // 0.7 / sqrt(0.58)
    const float a2c = 0.3939192985791676f;   // 0.3 / sqrt(0.58)
    #pragma unroll
    for (int i = 0; i < 4; ++i) {
        int row = bm + ty * 4 + i;
        size_t off = ((size_t)b * CIN + row) * NPIX + bn + tx * 4;
        float4 xv = *(const float4*)&x[off];
        float4 st;
        st.x = a1c * xv.x + a2c * acc[i][0];
        st.y = a1c * xv.y + a2c * acc[i][1];
        st.z = a1c * xv.z + a2c * acc[i][2];
        st.w = a1c * xv.w + a2c * acc[i][3];
        *(float4*)&out[off] = st;
    }
}

// ---------------- launch ----------------
extern "C" void kernel_launch(void* const* d_in, const int* in_sizes, int n_in,
                              void* d_out, int out_size) {
    const float* x    = (const float*)d_in[0];
    const float* wqkv = (const float*)d_in[1];
    const float* wout = (const float*)d_in[2];
    float* out = (float*)d_out;

    wnorm_kernel<<<CQKV, 256>>>(wqkv, 0);
    wnorm_kernel<<<CIN, 256>>>(wout, 1);
    qkv_gemm_kernel<<<dim3(NPIX / 64, CQKV / 64, BATCH), 256>>>(x);
    norm_split_kernel<<<(NBH * NPIX) / 256, 256>>>();
    attn_mma_kernel<<<dim3(NPIX / 64, NBH), 128>>>();
    out_gemm_kernel<<<dim3(NPIX / 64, CIN / 64, BATCH), 256>>>(x, out);
}

// round 3
// speedup vs baseline: 14.5053x; 1.9698x over previous
#include <cuda_runtime.h>
#include <cuda_fp16.h>
#include <math.h>

#define BATCH 2
#define CIN 256
#define CQKV 768
#define NHEADS 8
#define HDIM 32
#define NPIX 4096
#define EPSV 1e-4f
#define NBH (BATCH * NHEADS)

#define PADK 40
#define PADV 72
#define QSCF (0.17677669529663687f * 1.4426950408889634f)   // 1/sqrt(32) * log2(e)

// ---------------- device scratch ----------------
__device__ __half g_wqkvh[CQKV * CIN];        // normalized qkv weights fp16 [out][in]
__device__ __half g_wouth[CIN * CIN];         // normalized out weights fp16 [out][in]
__device__ __half g_xh[BATCH * NPIX * CIN];   // x transposed fp16 [b][pix][c]
__device__ __half g_qh[NBH * NPIX * HDIM];    // q * QSCF, [bh][pix][d]
__device__ __half g_kh[NBH * NPIX * HDIM];    // k, [bh][pix][d]
__device__ __half g_vt[NBH * HDIM * NPIX];    // v transposed, [bh][d][pix]
__device__ __half g_yh[BATCH * NPIX * CIN];   // attention out fp16 [b][pix][ch]

// ---------------- helpers ----------------
__device__ __forceinline__ void mma16816(float c[4],
                                         unsigned a0, unsigned a1, unsigned a2, unsigned a3,
                                         unsigned b0, unsigned b1) {
    asm volatile(
        "mma.sync.aligned.m16n8k16.row.col.f32.f16.f16.f32 "
        "{%0,%1,%2,%3}, {%4,%5,%6,%7}, {%8,%9}, {%0,%1,%2,%3};"
        : "+f"(c[0]), "+f"(c[1]), "+f"(c[2]), "+f"(c[3])
        : "r"(a0), "r"(a1), "r"(a2), "r"(a3), "r"(b0), "r"(b1));
}

__device__ __forceinline__ unsigned h2exp2(unsigned a) {
    unsigned d;
    asm("ex2.approx.f16x2 %0, %1;" : "=r"(d) : "r"(a));
    return d;
}

// ---------------- kernel 1: weight norm -> fp16 ----------------
__global__ void wnorm_kernel(const float* __restrict__ w, int which) {
    __half* o = which ? g_wouth : g_wqkvh;
    const int r = blockIdx.x;
    const int t = threadIdx.x;
    float v = w[r * CIN + t];
    __shared__ float red[256];
    red[t] = v * v;
    __syncthreads();
    #pragma unroll
    for (int s = 128; s > 0; s >>= 1) {
        if (t < s) red[t] += red[t + s];
        __syncthreads();
    }
    float n = sqrtf(red[0]);
    float scale = 0.0625f / (EPSV + 0.0625f * n);
    o[r * CIN + t] = __float2half_rn(v * scale);
}

// ---------------- kernel 2: x transpose + fp16 convert ----------------
// x [b][c][pix] fp32 -> g_xh [b][pix][c] fp16. 32x32 tiles.
__global__ void __launch_bounds__(256) xpose_kernel(const float* __restrict__ x) {
    __shared__ float t[32][33];
    const int px0 = blockIdx.x * 32;
    const int c0  = blockIdx.y * 32;
    const int b   = blockIdx.z;
    const int tx = threadIdx.x & 31, ty = threadIdx.x >> 5;
    #pragma unroll
    for (int i = 0; i < 4; ++i) {
        int c = c0 + ty + i * 8;
        t[ty + i * 8][tx] = x[((size_t)b * CIN + c) * NPIX + px0 + tx];
    }
    __syncthreads();
    #pragma unroll
    for (int i = 0; i < 4; ++i) {
        int pix = px0 + ty + i * 8;
        g_xh[((size_t)b * NPIX + pix) * CIN + c0 + tx] = __float2half_rn(t[tx][ty + i * 8]);
    }
}

// ---------------- kernel 3: fused QKV HMMA GEMM + pixel-norm ----------------
// C[pix][ch] = x[pix][:] . W[ch][:].  Block: 128 pixels x 64 channels (2 head-chunks),
// K=256.  4 warps, warp = 32 pixels x 64 channels.
__global__ void __launch_bounds__(128) qkv_fused_kernel() {
    const int px0 = blockIdx.x * 128;
    const int by  = blockIdx.y;           // 0..11 : pair of chunks (2*by, 2*by+1)
    const int b   = blockIdx.z;
    const int sec = by >> 2;              // 0=q, 1=k, 2=v
    const int h0  = (2 * by) & 7;

    const int tid = threadIdx.x;
    const int w = tid >> 5, lane = tid & 31;
    const int lq = lane >> 2, lr = lane & 3;

    __shared__ __half sX[128 * 72];       // [pix][k64]
    __shared__ __half sW[64 * 72];        // [ch][k64]

    float acc[2][8][4];
    #pragma unroll
    for (int i = 0; i < 2; ++i)
        #pragma unroll
        for (int j = 0; j < 8; ++j)
            #pragma unroll
            for (int q = 0; q < 4; ++q) acc[i][j][q] = 0.f;

    const __half* Xg = g_xh + ((size_t)b * NPIX + px0) * CIN;

    for (int kc = 0; kc < 4; ++kc) {
        __syncthreads();
        // load x tile [128][64]
        #pragma unroll
        for (int i = tid; i < 1024; i += 128) {
            int row = i >> 3, seg = i & 7;
            *(uint4*)&sX[row * 72 + seg * 8] =
                *(const uint4*)(Xg + (size_t)row * CIN + kc * 64 + seg * 8);
        }
        // load W tile [64][64]
        #pragma unroll
        for (int i = tid; i < 512; i += 128) {
            int n = i >> 3, seg = i & 7;
            int hh = h0 + (n >> 5);
            int wrow = sec * 256 + hh * 32 + (n & 31);
            *(uint4*)&sW[n * 72 + seg * 8] =
                *(const uint4*)(g_wqkvh + (size_t)wrow * CIN + kc * 64 + seg * 8);
        }
        __syncthreads();

        #pragma unroll
        for (int ks = 0; ks < 4; ++ks) {
            int kk0 = ks * 16;
            unsigned a[2][4];
            #pragma unroll
            for (int mt = 0; mt < 2; ++mt) {
                int am = w * 32 + mt * 16;
                a[mt][0] = *(unsigned*)&sX[(am + lq) * 72 + kk0 + lr * 2];
                a[mt][1] = *(unsigned*)&sX[(am + lq + 8) * 72 + kk0 + lr * 2];
                a[mt][2] = *(unsigned*)&sX[(am + lq) * 72 + kk0 + lr * 2 + 8];
                a[mt][3] = *(unsigned*)&sX[(am + lq + 8) * 72 + kk0 + lr * 2 + 8];
            }
            #pragma unroll
            for (int nt = 0; nt < 8; ++nt) {
                int n = nt * 8 + lq;
                unsigned b0 = *(unsigned*)&sW[n * 72 + kk0 + lr * 2];
                unsigned b1 = *(unsigned*)&sW[n * 72 + kk0 + lr * 2 + 8];
                #pragma unroll
                for (int mt = 0; mt < 2; ++mt)
                    mma16816(acc[mt][nt], a[mt][0], a[mt][1], a[mt][2], a[mt][3], b0, b1);
            }
        }
    }

    // ---- epilogue: per-pixel (row) RMS over each 32-channel chunk, store fp16 ----
    #pragma unroll
    for (int mt = 0; mt < 2; ++mt) {
        #pragma unroll
        for (int ch = 0; ch < 2; ++ch) {          // chunk: nt 0..3 or 4..7
            float ss0 = 0.f, ss1 = 0.f;
            #pragma unroll
            for (int nt4 = 0; nt4 < 4; ++nt4) {
                int nt = ch * 4 + nt4;
                ss0 += acc[mt][nt][0] * acc[mt][nt][0] + acc[mt][nt][1] * acc[mt][nt][1];
                ss1 += acc[mt][nt][2] * acc[mt][nt][2] + acc[mt][nt][3] * acc[mt][nt][3];
            }
            ss0 += __shfl_xor_sync(0xffffffffu, ss0, 1);
            ss0 += __shfl_xor_sync(0xffffffffu, ss0, 2);
            ss1 += __shfl_xor_sync(0xffffffffu, ss1, 1);
            ss1 += __shfl_xor_sync(0xffffffffu, ss1, 2);
            float sc0 = rsqrtf(ss0 * (1.0f / 32.0f) + EPSV);
            float sc1 = rsqrtf(ss1 * (1.0f / 32.0f) + EPSV);
            if (sec == 0) { sc0 *= QSCF; sc1 *= QSCF; }

            int hh = h0 + ch;
            int bh = b * NHEADS + hh;
            int pix0r = px0 + w * 32 + mt * 16 + lq;    // row for c0/c1
            int pix1r = pix0r + 8;                       // row for c2/c3

            if (sec == 2) {
                // v: [bh][d][pix], scattered half stores
                #pragma unroll
                for (int nt4 = 0; nt4 < 4; ++nt4) {
                    int nt = ch * 4 + nt4;
                    int d = nt4 * 8 + lr * 2;
                    __half* base = g_vt + (size_t)bh * HDIM * NPIX;
                    base[(size_t)(d)     * NPIX + pix0r] = __float2half_rn(acc[mt][nt][0] * sc0);
                    base[(size_t)(d + 1) * NPIX + pix0r] = __float2half_rn(acc[mt][nt][1] * sc0);
                    base[(size_t)(d)     * NPIX + pix1r] = __float2half_rn(acc[mt][nt][2] * sc1);
                    base[(size_t)(d + 1) * NPIX + pix1r] = __float2half_rn(acc[mt][nt][3] * sc1);
                }
            } else {
                __half* dst = (sec == 0) ? g_qh : g_kh;
                __half* r0p = dst + ((size_t)bh * NPIX + pix0r) * HDIM;
                __half* r1p = dst + ((size_t)bh * NPIX + pix1r) * HDIM;
                #pragma unroll
                for (int nt4 = 0; nt4 < 4; ++nt4) {
                    int nt = ch * 4 + nt4;
                    int d = nt4 * 8 + lr * 2;
                    *(__half2*)(r0p + d) = __floats2half2_rn(acc[mt][nt][0] * sc0,
                                                             acc[mt][nt][1] * sc0);
                    *(__half2*)(r1p + d) = __floats2half2_rn(acc[mt][nt][2] * sc1,
                                                             acc[mt][nt][3] * sc1);
                }
            }
        }
    }
}

// ---------------- kernel 4: flash attention (no-max, f16x2 exp2) ----------------
// grid (32 qtiles of 128 rows, 16 bh), 256 threads = 8 warps.
__global__ void __launch_bounds__(256) attn_mma_kernel() {
    const int qb = blockIdx.x;
    const int bh = blockIdx.y;
    const int tid = threadIdx.x;
    const int w = tid >> 5, lane = tid & 31;
    const int lq = lane >> 2, lr = lane & 3;

    const __half* Qg = g_qh + ((size_t)bh * NPIX + qb * 128) * HDIM;
    const __half* Kg = g_kh + (size_t)bh * NPIX * HDIM;
    const __half* Vg = g_vt + (size_t)bh * HDIM * NPIX;

    __shared__ __half sQ[128 * PADK];
    __shared__ __half sK[64 * PADK];
    __shared__ __half sVt[32 * PADV];

    // load Q tile (128x32)
    #pragma unroll
    for (int i = tid; i < 512; i += 256) {
        int row = i >> 2, seg = i & 3;
        *(uint4*)&sQ[row * PADK + seg * 8] = *(const uint4*)(Qg + row * 32 + seg * 8);
    }
    __syncthreads();

    const int r0 = w * 16 + lq;
    const int r1 = r0 + 8;
    unsigned qf[2][4];
    #pragma unroll
    for (int ks = 0; ks < 2; ++ks) {
        qf[ks][0] = *(unsigned*)&sQ[r0 * PADK + ks * 16 + lr * 2];
        qf[ks][1] = *(unsigned*)&sQ[r1 * PADK + ks * 16 + lr * 2];
        qf[ks][2] = *(unsigned*)&sQ[r0 * PADK + ks * 16 + lr * 2 + 8];
        qf[ks][3] = *(unsigned*)&sQ[r1 * PADK + ks * 16 + lr * 2 + 8];
    }

    float l0 = 0.f, l1 = 0.f;
    float o[4][4];
    #pragma unroll
    for (int i = 0; i < 4; ++i)
        #pragma unroll
        for (int j = 0; j < 4; ++j) o[i][j] = 0.f;

    const __half2 bias8 = __floats2half2_rn(-8.f, -8.f);

    for (int kt = 0; kt < 64; ++kt) {
        __syncthreads();
        const __half* Kt = Kg + (size_t)kt * 64 * 32;
        #pragma unroll
        for (int i = tid; i < 256; i += 256) {
            int row = i >> 2, seg = i & 3;
            *(uint4*)&sK[row * PADK + seg * 8] = *(const uint4*)(Kt + row * 32 + seg * 8);
        }
        {
            int i = tid;
            if (i < 256) {
                int row = i >> 3, seg = i & 7;
                *(uint4*)&sVt[row * PADV + seg * 8] =
                    *(const uint4*)(Vg + (size_t)row * NPIX + kt * 64 + seg * 8);
            }
        }
        __syncthreads();

        // ---- S = Q K^T ----
        float s[8][4];
        #pragma unroll
        for (int j = 0; j < 8; ++j) {
            s[j][0] = s[j][1] = s[j][2] = s[j][3] = 0.f;
            #pragma unroll
            for (int ks = 0; ks < 2; ++ks) {
                int krow = j * 8 + lq;
                unsigned b0 = *(unsigned*)&sK[krow * PADK + ks * 16 + lr * 2];
                unsigned b1 = *(unsigned*)&sK[krow * PADK + ks * 16 + lr * 2 + 8];
                mma16816(s[j], qf[ks][0], qf[ks][1], qf[ks][2], qf[ks][3], b0, b1);
            }
        }

        // ---- P = exp2(S - 8), f16x2; accumulate l in half2 per-iter ----
        unsigned pa[4][4];
        __half2 acc01 = __floats2half2_rn(0.f, 0.f);
        __half2 acc23 = __floats2half2_rn(0.f, 0.f);
        #pragma unroll
        for (int j = 0; j < 8; ++j) {
            __half2 h01 = __hadd2(__floats2half2_rn(s[j][0], s[j][1]), bias8);
            __half2 h23 = __hadd2(__floats2half2_rn(s[j][2], s[j][3]), bias8);
            unsigned e01 = h2exp2(*(unsigned*)&h01);
            unsigned e23 = h2exp2(*(unsigned*)&h23);
            acc01 = __hadd2(acc01, *(__half2*)&e01);
            acc23 = __hadd2(acc23, *(__half2*)&e23);
            int kk2 = j >> 1, hi = (j & 1) * 2;
            pa[kk2][hi + 0] = e01;
            pa[kk2][hi + 1] = e23;
        }
        l0 += __low2float(acc01) + __high2float(acc01);
        l1 += __low2float(acc23) + __high2float(acc23);

        // ---- O += P V ----
        #pragma unroll
        for (int kk2 = 0; kk2 < 4; ++kk2) {
            #pragma unroll
            for (int nt = 0; nt < 4; ++nt) {
                int drow = nt * 8 + lq;
                unsigned b0 = *(unsigned*)&sVt[drow * PADV + kk2 * 16 + lr * 2];
                unsigned b1 = *(unsigned*)&sVt[drow * PADV + kk2 * 16 + lr * 2 + 8];
                mma16816(o[nt], pa[kk2][0], pa[kk2][1], pa[kk2][2], pa[kk2][3], b0, b1);
            }
        }
    }

    l0 += __shfl_xor_sync(0xffffffffu, l0, 1);
    l0 += __shfl_xor_sync(0xffffffffu, l0, 2);
    l1 += __shfl_xor_sync(0xffffffffu, l1, 1);
    l1 += __shfl_xor_sync(0xffffffffu, l1, 2);
    float inv0 = 1.0f / l0, inv1 = 1.0f / l1;

    int b = bh >> 3, h = bh & 7;
    __half* O0 = g_yh + ((size_t)b * NPIX + qb * 128 + r0) * CIN + h * 32;
    __half* O1 = g_yh + ((size_t)b * NPIX + qb * 128 + r1) * CIN + h * 32;
    #pragma unroll
    for (int nt = 0; nt < 4; ++nt) {
        int col = nt * 8 + lr * 2;
        *(__half2*)(O0 + col) = __floats2half2_rn(o[nt][0] * inv0, o[nt][1] * inv0);
        *(__half2*)(O1 + col) = __floats2half2_rn(o[nt][2] * inv1, o[nt][3] * inv1);
    }
}

// ---------------- kernel 5: out GEMM HMMA + mp_add ----------------
// C[ch][pix] = Wout[ch][:] . y[pix][:].  Block: 128 ch x 64 pix, 8 warps (4x2).
__global__ void __launch_bounds__(256) out_gemm_kernel(const float* __restrict__ x,
                                                       float* __restrict__ out) {
    const int px0 = blockIdx.x * 64;
    const int cm0 = blockIdx.y * 128;
    const int b   = blockIdx.z;

    const int tid = threadIdx.x;
    const int w = tid >> 5, lane = tid & 31;
    const int lq = lane >> 2, lr = lane & 3;
    const int wm = w & 3, wn = w >> 2;

    __shared__ __half sW2[128 * 72];      // [ch][k64]
    __shared__ __half sY[64 * 72];        // [pix][k64]

    float acc[2][4][4];
    #pragma unroll
    for (int i = 0; i < 2; ++i)
        #pragma unroll
        for (int j = 0; j < 4; ++j)
            #pragma unroll
            for (int q = 0; q < 4; ++q) acc[i][j][q] = 0.f;

    const __half* Yg = g_yh + ((size_t)b * NPIX + px0) * CIN;

    for (int kc = 0; kc < 4; ++kc) {
        __syncthreads();
        #pragma unroll
        for (int i = tid; i < 1024; i += 256) {
            int m = i >> 3, seg = i & 7;
            *(uint4*)&sW2[m * 72 + seg * 8] =
                *(const uint4*)(g_wouth + (size_t)(cm0 + m) * CIN + kc * 64 + seg * 8);
        }
        #pragma unroll
        for (int i = tid; i < 512; i += 256) {
            int n = i >> 3, seg = i & 7;
            *(uint4*)&sY[n * 72 + seg * 8] =
                *(const uint4*)(Yg + (size_t)n * CIN + kc * 64 + seg * 8);
        }
        __syncthreads();

        #pragma unroll
        for (int ks = 0; ks < 4; ++ks) {
            int kk0 = ks * 16;
            unsigned a[2][4];
            #pragma unroll
            for (int mt = 0; mt < 2; ++mt) {
                int am = wm * 32 + mt * 16;
                a[mt][0] = *(unsigned*)&sW2[(am + lq) * 72 + kk0 + lr * 2];
                a[mt][1] = *(unsigned*)&sW2[(am + lq + 8) * 72 + kk0 + lr * 2];
                a[mt][2] = *(unsigned*)&sW2[(am + lq) * 72 + kk0 + lr * 2 + 8];
                a[mt][3] = *(unsigned*)&sW2[(am + lq + 8) * 72 + kk0 + lr * 2 + 8];
            }
            #pragma unroll
            for (int nt = 0; nt < 4; ++nt) {
                int n = wn * 32 + nt * 8 + lq;
                unsigned b0 = *(unsigned*)&sY[n * 72 + kk0 + lr * 2];
                unsigned b1 = *(unsigned*)&sY[n * 72 + kk0 + lr * 2 + 8];
                #pragma unroll
                for (int mt = 0; mt < 2; ++mt)
                    mma16816(acc[mt][nt], a[mt][0], a[mt][1], a[mt][2], a[mt][3], b0, b1);
            }
        }
    }

    const float a1c = 0.9191450300180579f;   // 0.7 / sqrt(0.58)
    const float a2c = 0.3939192985791676f;   // 0.3 / sqrt(0.58)
    #pragma unroll
    for (int mt = 0; mt < 2; ++mt) {
        #pragma unroll
        for (int nt = 0; nt < 4; ++nt) {
            int ch0 = cm0 + wm * 32 + mt * 16 + lq;
            int pix = px0 + wn * 32 + nt * 8 + lr * 2;
            #pragma unroll
            for (int rr = 0; rr < 2; ++rr) {
                int ch = ch0 + rr * 8;
                size_t off = ((size_t)b * CIN + ch) * NPIX + pix;
                float2 xv = *(const float2*)&x[off];
                float2 st;
                st.x = a1c * xv.x + a2c * acc[mt][nt][rr * 2 + 0];
                st.y = a1c * xv.y + a2c * acc[mt][nt][rr * 2 + 1];
                *(float2*)&out[off] = st;
            }
        }
    }
}

// ---------------- launch ----------------
extern "C" void kernel_launch(void* const* d_in, const int* in_sizes, int n_in,
                              void* d_out, int out_size) {
    const float* x    = (const float*)d_in[0];
    const float* wqkv = (const float*)d_in[1];
    const float* wout = (const float*)d_in[2];
    float* out = (float*)d_out;

    wnorm_kernel<<<CQKV, 256>>>(wqkv, 0);
    wnorm_kernel<<<CIN, 256>>>(wout, 1);
    xpose_kernel<<<dim3(NPIX / 32, CIN / 32, BATCH), 256>>>(x);
    qkv_fused_kernel<<<dim3(NPIX / 128, 12, BATCH), 128>>>();
    attn_mma_kernel<<<dim3(NPIX / 128, NBH), 256>>>();
    out_gemm_kernel<<<dim3(NPIX / 64, CIN / 128, BATCH), 256>>>(x, out);
}

// round 4
// speedup vs baseline: 15.0842x; 1.0399x over previous
#include <cuda_runtime.h>
#include <cuda_fp16.h>
#include <math.h>

#define BATCH 2
#define CIN 256
#define CQKV 768
#define NHEADS 8
#define HDIM 32
#define NPIX 4096
#define EPSV 1e-4f
#define NBH (BATCH * NHEADS)

#define PADK 40
#define PADV 72
#define QSCF (0.17677669529663687f * 1.4426950408889634f)   // 1/sqrt(32) * log2(e)

// ---------------- device scratch ----------------
__device__ __half g_wqkvh[CQKV * CIN];
__device__ __half g_wouth[CIN * CIN];
__device__ __half g_xh[BATCH * NPIX * CIN];
__device__ __half g_qh[NBH * NPIX * HDIM];
__device__ __half g_kh[NBH * NPIX * HDIM];
__device__ __half g_vt[NBH * HDIM * NPIX];
__device__ __half g_yh[BATCH * NPIX * CIN];

// ---------------- helpers ----------------
__device__ __forceinline__ void mma16816(float c[4],
                                         unsigned a0, unsigned a1, unsigned a2, unsigned a3,
                                         unsigned b0, unsigned b1) {
    asm volatile(
        "mma.sync.aligned.m16n8k16.row.col.f32.f16.f16.f32 "
        "{%0,%1,%2,%3}, {%4,%5,%6,%7}, {%8,%9}, {%0,%1,%2,%3};"
        : "+f"(c[0]), "+f"(c[1]), "+f"(c[2]), "+f"(c[3])
        : "r"(a0), "r"(a1), "r"(a2), "r"(a3), "r"(b0), "r"(b1));
}

__device__ __forceinline__ unsigned h2exp2(unsigned a) {
    unsigned d;
    asm("ex2.approx.f16x2 %0, %1;" : "=r"(d) : "r"(a));
    return d;
}

// ---------------- kernel 1: weight norm -> fp16 ----------------
__global__ void wnorm_kernel(const float* __restrict__ w, int which) {
    __half* o = which ? g_wouth : g_wqkvh;
    const int r = blockIdx.x;
    const int t = threadIdx.x;
    float v = w[r * CIN + t];
    __shared__ float red[256];
    red[t] = v * v;
    __syncthreads();
    #pragma unroll
    for (int s = 128; s > 0; s >>= 1) {
        if (t < s) red[t] += red[t + s];
        __syncthreads();
    }
    float n = sqrtf(red[0]);
    float scale = 0.0625f / (EPSV + 0.0625f * n);
    o[r * CIN + t] = __float2half_rn(v * scale);
}

// ---------------- kernel 2: x transpose + fp16 convert ----------------
__global__ void __launch_bounds__(256) xpose_kernel(const float* __restrict__ x) {
    __shared__ float t[32][33];
    const int px0 = blockIdx.x * 32;
    const int c0  = blockIdx.y * 32;
    const int b   = blockIdx.z;
    const int tx = threadIdx.x & 31, ty = threadIdx.x >> 5;
    #pragma unroll
    for (int i = 0; i < 4; ++i) {
        int c = c0 + ty + i * 8;
        t[ty + i * 8][tx] = x[((size_t)b * CIN + c) * NPIX + px0 + tx];
    }
    __syncthreads();
    #pragma unroll
    for (int i = 0; i < 4; ++i) {
        int pix = px0 + ty + i * 8;
        g_xh[((size_t)b * NPIX + pix) * CIN + c0 + tx] = __float2half_rn(t[tx][ty + i * 8]);
    }
}

// ---------------- kernel 3: fused QKV HMMA GEMM + pixel-norm ----------------
// Block: 128 pixels x 128 channels, 8 warps (4 pix-groups x 2 ch-groups).
// Warp = 32 pixels x 64 channels (2 head-chunks). K=256.
__global__ void __launch_bounds__(256) qkv_fused_kernel() {
    const int px0 = blockIdx.x * 128;
    const int by  = blockIdx.y;            // 0..5 : 128-channel slab
    const int b   = blockIdx.z;
    const int sec = by >> 1;               // 0=q, 1=k, 2=v
    const int cofs = (by & 1) * 128;       // channel offset within section

    const int tid = threadIdx.x;
    const int w = tid >> 5, lane = tid & 31;
    const int lq = lane >> 2, lr = lane & 3;
    const int wm = w & 3, wn = w >> 2;

    __shared__ __half sX[128 * 72];        // [pix][k64]
    __shared__ __half sW[128 * 72];        // [ch][k64]

    float acc[2][8][4];
    #pragma unroll
    for (int i = 0; i < 2; ++i)
        #pragma unroll
        for (int j = 0; j < 8; ++j)
            #pragma unroll
            for (int q = 0; q < 4; ++q) acc[i][j][q] = 0.f;

    const __half* Xg = g_xh + ((size_t)b * NPIX + px0) * CIN;
    const __half* Wg = g_wqkvh + (size_t)(sec * 256 + cofs) * CIN;

    for (int kc = 0; kc < 4; ++kc) {
        __syncthreads();
        #pragma unroll
        for (int i = tid; i < 1024; i += 256) {
            int row = i >> 3, seg = i & 7;
            *(uint4*)&sX[row * 72 + seg * 8] =
                *(const uint4*)(Xg + (size_t)row * CIN + kc * 64 + seg * 8);
        }
        #pragma unroll
        for (int i = tid; i < 1024; i += 256) {
            int n = i >> 3, seg = i & 7;
            *(uint4*)&sW[n * 72 + seg * 8] =
                *(const uint4*)(Wg + (size_t)n * CIN + kc * 64 + seg * 8);
        }
        __syncthreads();

        #pragma unroll
        for (int ks = 0; ks < 4; ++ks) {
            int kk0 = ks * 16;
            unsigned a[2][4];
            #pragma unroll
            for (int mt = 0; mt < 2; ++mt) {
                int am = wm * 32 + mt * 16;
                a[mt][0] = *(unsigned*)&sX[(am + lq) * 72 + kk0 + lr * 2];
                a[mt][1] = *(unsigned*)&sX[(am + lq + 8) * 72 + kk0 + lr * 2];
                a[mt][2] = *(unsigned*)&sX[(am + lq) * 72 + kk0 + lr * 2 + 8];
                a[mt][3] = *(unsigned*)&sX[(am + lq + 8) * 72 + kk0 + lr * 2 + 8];
            }
            #pragma unroll
            for (int nt = 0; nt < 8; ++nt) {
                int n = wn * 64 + nt * 8 + lq;
                unsigned b0 = *(unsigned*)&sW[n * 72 + kk0 + lr * 2];
                unsigned b1 = *(unsigned*)&sW[n * 72 + kk0 + lr * 2 + 8];
                #pragma unroll
                for (int mt = 0; mt < 2; ++mt)
                    mma16816(acc[mt][nt], a[mt][0], a[mt][1], a[mt][2], a[mt][3], b0, b1);
            }
        }
    }

    // ---- epilogue: per-pixel RMS over each 32-channel chunk, store fp16 ----
    #pragma unroll
    for (int mt = 0; mt < 2; ++mt) {
        #pragma unroll
        for (int ch = 0; ch < 2; ++ch) {
            float ss0 = 0.f, ss1 = 0.f;
            #pragma unroll
            for (int nt4 = 0; nt4 < 4; ++nt4) {
                int nt = ch * 4 + nt4;
                ss0 += acc[mt][nt][0] * acc[mt][nt][0] + acc[mt][nt][1] * acc[mt][nt][1];
                ss1 += acc[mt][nt][2] * acc[mt][nt][2] + acc[mt][nt][3] * acc[mt][nt][3];
            }
            ss0 += __shfl_xor_sync(0xffffffffu, ss0, 1);
            ss0 += __shfl_xor_sync(0xffffffffu, ss0, 2);
            ss1 += __shfl_xor_sync(0xffffffffu, ss1, 1);
            ss1 += __shfl_xor_sync(0xffffffffu, ss1, 2);
            float sc0 = rsqrtf(ss0 * (1.0f / 32.0f) + EPSV);
            float sc1 = rsqrtf(ss1 * (1.0f / 32.0f) + EPSV);
            if (sec == 0) { sc0 *= QSCF; sc1 *= QSCF; }

            int hh = (cofs >> 5) + wn * 2 + ch;          // head index 0..7
            int bh = b * NHEADS + hh;
            int pix0r = px0 + wm * 32 + mt * 16 + lq;
            int pix1r = pix0r + 8;

            if (sec == 2) {
                #pragma unroll
                for (int nt4 = 0; nt4 < 4; ++nt4) {
                    int nt = ch * 4 + nt4;
                    int d = nt4 * 8 + lr * 2;
                    __half* base = g_vt + (size_t)bh * HDIM * NPIX;
                    base[(size_t)(d)     * NPIX + pix0r] = __float2half_rn(acc[mt][nt][0] * sc0);
                    base[(size_t)(d + 1) * NPIX + pix0r] = __float2half_rn(acc[mt][nt][1] * sc0);
                    base[(size_t)(d)     * NPIX + pix1r] = __float2half_rn(acc[mt][nt][2] * sc1);
                    base[(size_t)(d + 1) * NPIX + pix1r] = __float2half_rn(acc[mt][nt][3] * sc1);
                }
            } else {
                __half* dst = (sec == 0) ? g_qh : g_kh;
                __half* r0p = dst + ((size_t)bh * NPIX + pix0r) * HDIM;
                __half* r1p = dst + ((size_t)bh * NPIX + pix1r) * HDIM;
                #pragma unroll
                for (int nt4 = 0; nt4 < 4; ++nt4) {
                    int nt = ch * 4 + nt4;
                    int d = nt4 * 8 + lr * 2;
                    *(__half2*)(r0p + d) = __floats2half2_rn(acc[mt][nt][0] * sc0,
                                                             acc[mt][nt][1] * sc0);
                    *(__half2*)(r1p + d) = __floats2half2_rn(acc[mt][nt][2] * sc1,
                                                             acc[mt][nt][3] * sc1);
                }
            }
        }
    }
}

// ---------------- kernel 4: flash attention, double-buffered ----------------
// grid (32 qtiles of 128 rows, 16 bh), 256 threads = 8 warps.
__global__ void __launch_bounds__(256) attn_mma_kernel() {
    const int qb = blockIdx.x;
    const int bh = blockIdx.y;
    const int tid = threadIdx.x;
    const int w = tid >> 5, lane = tid & 31;
    const int lq = lane >> 2, lr = lane & 3;

    const __half* Qg = g_qh + ((size_t)bh * NPIX + qb * 128) * HDIM;
    const __half* Kg = g_kh + (size_t)bh * NPIX * HDIM;
    const __half* Vg = g_vt + (size_t)bh * HDIM * NPIX;

    __shared__ __half sQ[128 * PADK];
    __shared__ __half sK[2][64 * PADK];
    __shared__ __half sVt[2][32 * PADV];

    // per-thread staging slots
    const int krow = tid >> 2, kseg = tid & 3;     // K: 256 uint4
    const int vrow = tid >> 3, vseg = tid & 7;     // V: 256 uint4

    // load Q tile (128x32) + prime buffer 0
    #pragma unroll
    for (int i = tid; i < 512; i += 256) {
        int row = i >> 2, seg = i & 3;
        *(uint4*)&sQ[row * PADK + seg * 8] = *(const uint4*)(Qg + row * 32 + seg * 8);
    }
    *(uint4*)&sK[0][krow * PADK + kseg * 8] =
        *(const uint4*)(Kg + (size_t)krow * 32 + kseg * 8);
    *(uint4*)&sVt[0][vrow * PADV + vseg * 8] =
        *(const uint4*)(Vg + (size_t)vrow * NPIX + vseg * 8);
    __syncthreads();

    const int r0 = w * 16 + lq;
    const int r1 = r0 + 8;
    unsigned qf[2][4];
    #pragma unroll
    for (int ks = 0; ks < 2; ++ks) {
        qf[ks][0] = *(unsigned*)&sQ[r0 * PADK + ks * 16 + lr * 2];
        qf[ks][1] = *(unsigned*)&sQ[r1 * PADK + ks * 16 + lr * 2];
        qf[ks][2] = *(unsigned*)&sQ[r0 * PADK + ks * 16 + lr * 2 + 8];
        qf[ks][3] = *(unsigned*)&sQ[r1 * PADK + ks * 16 + lr * 2 + 8];
    }

    float l0 = 0.f, l1 = 0.f;
    float o[4][4];
    #pragma unroll
    for (int i = 0; i < 4; ++i)
        #pragma unroll
        for (int j = 0; j < 4; ++j) o[i][j] = 0.f;

    const __half2 bias8 = __floats2half2_rn(-8.f, -8.f);

    for (int kt = 0; kt < 64; ++kt) {
        const int cur = kt & 1;
        uint4 kst, vst;
        if (kt < 63) {
            kst = *(const uint4*)(Kg + (size_t)((kt + 1) * 64 + krow) * 32 + kseg * 8);
            vst = *(const uint4*)(Vg + (size_t)vrow * NPIX + (kt + 1) * 64 + vseg * 8);
        }

        // ---- S = Q K^T ----
        float s[8][4];
        #pragma unroll
        for (int j = 0; j < 8; ++j) {
            s[j][0] = s[j][1] = s[j][2] = s[j][3] = 0.f;
            #pragma unroll
            for (int ks = 0; ks < 2; ++ks) {
                int kr = j * 8 + lq;
                unsigned b0 = *(unsigned*)&sK[cur][kr * PADK + ks * 16 + lr * 2];
                unsigned b1 = *(unsigned*)&sK[cur][kr * PADK + ks * 16 + lr * 2 + 8];
                mma16816(s[j], qf[ks][0], qf[ks][1], qf[ks][2], qf[ks][3], b0, b1);
            }
        }

        // ---- P = exp2(S - 8), f16x2 ----
        unsigned pa[4][4];
        __half2 acc01 = __floats2half2_rn(0.f, 0.f);
        __half2 acc23 = __floats2half2_rn(0.f, 0.f);
        #pragma unroll
        for (int j = 0; j < 8; ++j) {
            __half2 h01 = __hadd2(__floats2half2_rn(s[j][0], s[j][1]), bias8);
            __half2 h23 = __hadd2(__floats2half2_rn(s[j][2], s[j][3]), bias8);
            unsigned e01 = h2exp2(*(unsigned*)&h01);
            unsigned e23 = h2exp2(*(unsigned*)&h23);
            acc01 = __hadd2(acc01, *(__half2*)&e01);
            acc23 = __hadd2(acc23, *(__half2*)&e23);
            int kk2 = j >> 1, hi = (j & 1) * 2;
            pa[kk2][hi + 0] = e01;
            pa[kk2][hi + 1] = e23;
        }
        l0 += __low2float(acc01) + __high2float(acc01);
        l1 += __low2float(acc23) + __high2float(acc23);

        // ---- O += P V ----
        #pragma unroll
        for (int kk2 = 0; kk2 < 4; ++kk2) {
            #pragma unroll
            for (int nt = 0; nt < 4; ++nt) {
                int drow = nt * 8 + lq;
                unsigned b0 = *(unsigned*)&sVt[cur][drow * PADV + kk2 * 16 + lr * 2];
                unsigned b1 = *(unsigned*)&sVt[cur][drow * PADV + kk2 * 16 + lr * 2 + 8];
                mma16816(o[nt], pa[kk2][0], pa[kk2][1], pa[kk2][2], pa[kk2][3], b0, b1);
            }
        }

        if (kt < 63) {
            *(uint4*)&sK[cur ^ 1][krow * PADK + kseg * 8] = kst;
            *(uint4*)&sVt[cur ^ 1][vrow * PADV + vseg * 8] = vst;
        }
        __syncthreads();
    }

    l0 += __shfl_xor_sync(0xffffffffu, l0, 1);
    l0 += __shfl_xor_sync(0xffffffffu, l0, 2);
    l1 += __shfl_xor_sync(0xffffffffu, l1, 1);
    l1 += __shfl_xor_sync(0xffffffffu, l1, 2);
    float inv0 = 1.0f / l0, inv1 = 1.0f / l1;

    int b = bh >> 3, h = bh & 7;
    __half* O0 = g_yh + ((size_t)b * NPIX + qb * 128 + r0) * CIN + h * 32;
    __half* O1 = g_yh + ((size_t)b * NPIX + qb * 128 + r1) * CIN + h * 32;
    #pragma unroll
    for (int nt = 0; nt < 4; ++nt) {
        int col = nt * 8 + lr * 2;
        *(__half2*)(O0 + col) = __floats2half2_rn(o[nt][0] * inv0, o[nt][1] * inv0);
        *(__half2*)(O1 + col) = __floats2half2_rn(o[nt][2] * inv1, o[nt][3] * inv1);
    }
}

// ---------------- kernel 5: out GEMM HMMA + mp_add ----------------
__global__ void __launch_bounds__(256) out_gemm_kernel(const float* __restrict__ x,
                                                       float* __restrict__ out) {
    const int px0 = blockIdx.x * 64;
    const int cm0 = blockIdx.y * 128;
    const int b   = blockIdx.z;

    const int tid = threadIdx.x;
    const int w = tid >> 5, lane = tid & 31;
    const int lq = lane >> 2, lr = lane & 3;
    const int wm = w & 3, wn = w >> 2;

    __shared__ __half sW2[128 * 72];
    __shared__ __half sY[64 * 72];

    float acc[2][4][4];
    #pragma unroll
    for (int i = 0; i < 2; ++i)
        #pragma unroll
        for (int j = 0; j < 4; ++j)
            #pragma unroll
            for (int q = 0; q < 4; ++q) acc[i][j][q] = 0.f;

    const __half* Yg = g_yh + ((size_t)b * NPIX + px0) * CIN;

    for (int kc = 0; kc < 4; ++kc) {
        __syncthreads();
        #pragma unroll
        for (int i = tid; i < 1024; i += 256) {
            int m = i >> 3, seg = i & 7;
            *(uint4*)&sW2[m * 72 + seg * 8] =
                *(const uint4*)(g_wouth + (size_t)(cm0 + m) * CIN + kc * 64 + seg * 8);
        }
        #pragma unroll
        for (int i = tid; i < 512; i += 256) {
            int n = i >> 3, seg = i & 7;
            *(uint4*)&sY[n * 72 + seg * 8] =
                *(const uint4*)(Yg + (size_t)n * CIN + kc * 64 + seg * 8);
        }
        __syncthreads();

        #pragma unroll
        for (int ks = 0; ks < 4; ++ks) {
            int kk0 = ks * 16;
            unsigned a[2][4];
            #pragma unroll
            for (int mt = 0; mt < 2; ++mt) {
                int am = wm * 32 + mt * 16;
                a[mt][0] = *(unsigned*)&sW2[(am + lq) * 72 + kk0 + lr * 2];
                a[mt][1] = *(unsigned*)&sW2[(am + lq + 8) * 72 + kk0 + lr * 2];
                a[mt][2] = *(unsigned*)&sW2[(am + lq) * 72 + kk0 + lr * 2 + 8];
                a[mt][3] = *(unsigned*)&sW2[(am + lq + 8) * 72 + kk0 + lr * 2 + 8];
            }
            #pragma unroll
            for (int nt = 0; nt < 4; ++nt) {
                int n = wn * 32 + nt * 8 + lq;
                unsigned b0 = *(unsigned*)&sY[n * 72 + kk0 + lr * 2];
                unsigned b1 = *(unsigned*)&sY[n * 72 + kk0 + lr * 2 + 8];
                #pragma unroll
                for (int mt = 0; mt < 2; ++mt)
                    mma16816(acc[mt][nt], a[mt][0], a[mt][1], a[mt][2], a[mt][3], b0, b1);
            }
        }
    }

    const float a1c = 0.9191450300180579f;
    const float a2c = 0.3939192985791676f;
    #pragma unroll
    for (int mt = 0; mt < 2; ++mt) {
        #pragma unroll
        for (int nt = 0; nt < 4; ++nt) {
            int ch0 = cm0 + wm * 32 + mt * 16 + lq;
            int pix = px0 + wn * 32 + nt * 8 + lr * 2;
            #pragma unroll
            for (int rr = 0; rr < 2; ++rr) {
                int ch = ch0 + rr * 8;
                size_t off = ((size_t)b * CIN + ch) * NPIX + pix;
                float2 xv = *(const float2*)&x[off];
                float2 st;
                st.x = a1c * xv.x + a2c * acc[mt][nt][rr * 2 + 0];
                st.y = a1c * xv.y + a2c * acc[mt][nt][rr * 2 + 1];
                *(float2*)&out[off] = st;
            }
        }
    }
}

// ---------------- launch ----------------
extern "C" void kernel_launch(void* const* d_in, const int* in_sizes, int n_in,
                              void* d_out, int out_size) {
    const float* x    = (const float*)d_in[0];
    const float* wqkv = (const float*)d_in[1];
    const float* wout = (const float*)d_in[2];
    float* out = (float*)d_out;

    wnorm_kernel<<<CQKV, 256>>>(wqkv, 0);
    wnorm_kernel<<<CIN, 256>>>(wout, 1);
    xpose_kernel<<<dim3(NPIX / 32, CIN / 32, BATCH), 256>>>(x);
    qkv_fused_kernel<<<dim3(NPIX / 128, 6, BATCH), 256>>>();
    attn_mma_kernel<<<dim3(NPIX / 128, NBH), 256>>>();
    out_gemm_kernel<<<dim3(NPIX / 64, CIN / 128, BATCH), 256>>>(x, out);
}